// round 1
// baseline (speedup 1.0000x reference)
#include <cuda_runtime.h>
#include <math.h>

#define H_DIM   4096
#define BATCH   64
#define T_STEPS 128
#define I_DIM   1024
#define NNZ_IH  131072
#define NNZ_HH  262144
#define ROWS_PER_BLK 8

// ---------------- scratch (device globals; no runtime allocation) ----------------
__device__ float g_xT[T_STEPS * I_DIM * BATCH];   // x transposed to (T, I, B)  32MB
__device__ float g_h[2][H_DIM * BATCH];           // ping-pong hidden state (H, B)
__device__ int   g_ih_ptr[H_DIM + 1];
__device__ int   g_hh_ptr[H_DIM + 1];
__device__ int   g_ih_col[NNZ_IH];
__device__ float g_ih_val[NNZ_IH];
__device__ int   g_hh_col[NNZ_HH];
__device__ float g_hh_val[NNZ_HH];
__device__ int   g_cnt[2 * H_DIM];

// ---------------- setup kernels ----------------
__global__ void k_zero_all() {
    int idx = blockIdx.x * blockDim.x + threadIdx.x;
    if (idx < H_DIM * BATCH) g_h[0][idx] = 0.0f;
    if (idx < 2 * H_DIM)     g_cnt[idx]  = 0;
}

__global__ void k_zero_cnt() {
    int idx = blockIdx.x * blockDim.x + threadIdx.x;
    if (idx < 2 * H_DIM) g_cnt[idx] = 0;
}

__global__ void k_hist(const int* __restrict__ ih_rows, const int* __restrict__ hh_rows) {
    int k = blockIdx.x * blockDim.x + threadIdx.x;
    if (k < NNZ_IH) atomicAdd(&g_cnt[ih_rows[k]], 1);
    if (k < NNZ_HH) atomicAdd(&g_cnt[H_DIM + hh_rows[k]], 1);
}

// exclusive scan of 4096 counts -> row pointers (one block per matrix)
__global__ void k_scan() {
    __shared__ int sums[1024];
    int which = blockIdx.x;              // 0 = ih, 1 = hh
    int* cnt = &g_cnt[which * H_DIM];
    int* ptr = which ? g_hh_ptr : g_ih_ptr;
    int tid  = threadIdx.x;
    int base = tid * 4;
    int v0 = cnt[base + 0];
    int v1 = cnt[base + 1];
    int v2 = cnt[base + 2];
    int v3 = cnt[base + 3];
    int local = v0 + v1 + v2 + v3;
    sums[tid] = local;
    __syncthreads();
    for (int off = 1; off < 1024; off <<= 1) {
        int t = (tid >= off) ? sums[tid - off] : 0;
        __syncthreads();
        sums[tid] += t;
        __syncthreads();
    }
    int excl = sums[tid] - local;
    ptr[base + 0] = excl;
    ptr[base + 1] = excl + v0;
    ptr[base + 2] = excl + v0 + v1;
    ptr[base + 3] = excl + v0 + v1 + v2;
    if (tid == 1023) ptr[H_DIM] = sums[1023];
}

__global__ void k_scatter(const int* __restrict__ ih_rows, const int* __restrict__ ih_cols,
                          const float* __restrict__ ih_vals,
                          const int* __restrict__ hh_rows, const int* __restrict__ hh_cols,
                          const float* __restrict__ hh_vals) {
    int k = blockIdx.x * blockDim.x + threadIdx.x;
    if (k < NNZ_IH) {
        int r = ih_rows[k];
        int p = g_ih_ptr[r] + atomicAdd(&g_cnt[r], 1);
        g_ih_col[p] = ih_cols[k];
        g_ih_val[p] = ih_vals[k];
    }
    if (k < NNZ_HH) {
        int r = hh_rows[k];
        int p = g_hh_ptr[r] + atomicAdd(&g_cnt[H_DIM + r], 1);
        g_hh_col[p] = hh_cols[k];
        g_hh_val[p] = hh_vals[k];
    }
}

// x (B,T,I) -> g_xT (T,I,B): makes per-entry batch gathers contiguous (256B)
__global__ void k_transpose_x(const float* __restrict__ x) {
    __shared__ float tile[32][33];
    int t  = blockIdx.z;
    int i0 = blockIdx.x * 32;
    int b0 = blockIdx.y * 32;
    // read x[b][t][i], coalesced along i
    int b = b0 + threadIdx.y;
    int i = i0 + threadIdx.x;
    tile[threadIdx.y][threadIdx.x] =
        x[((size_t)b * T_STEPS + t) * I_DIM + i];
    __syncthreads();
    // write xT[t][i][b], coalesced along b
    int iw = i0 + threadIdx.y;
    int bw = b0 + threadIdx.x;
    g_xT[((size_t)t * I_DIM + iw) * BATCH + bw] = tile[threadIdx.x][threadIdx.y];
}

// ---------------- per-timestep kernel ----------------
// block: (64 batch lanes, ROWS_PER_BLK rows). Each warp = one row, 32 consecutive
// batch lanes -> every gather of h/x is a single coalesced 128B line.
__global__ void k_step(const float* __restrict__ bias, float* __restrict__ out,
                       int t, int prev) {
    const float* __restrict__ hp = g_h[prev];
    float* __restrict__ hn = g_h[prev ^ 1];
    const float* __restrict__ xt = &g_xT[(size_t)t * I_DIM * BATCH];

    int b = threadIdx.x;                                  // 0..63
    int r = blockIdx.x * ROWS_PER_BLK + threadIdx.y;      // row

    float acc = bias[r];

    int k0 = g_ih_ptr[r];
    int k1 = g_ih_ptr[r + 1];
    #pragma unroll 4
    for (int k = k0; k < k1; k++) {
        acc += g_ih_val[k] * xt[g_ih_col[k] * BATCH + b];
    }

    k0 = g_hh_ptr[r];
    k1 = g_hh_ptr[r + 1];
    #pragma unroll 4
    for (int k = k0; k < k1; k++) {
        acc += g_hh_val[k] * hp[g_hh_col[k] * BATCH + b];
    }

    float hv = tanhf(acc);
    hn[r * BATCH + b] = hv;                               // coalesced (H,B) write

    // transpose within block for sector-efficient out (B,T,H) writes
    __shared__ float tile[BATCH][ROWS_PER_BLK + 1];
    tile[b][threadIdx.y] = hv;
    __syncthreads();
    int lin = threadIdx.y * BATCH + threadIdx.x;          // 0..511
    int bb  = lin >> 3;                                   // 0..63
    int rr  = lin & 7;                                    // 0..7
    out[(size_t)bb * (T_STEPS * H_DIM) + (size_t)t * H_DIM
        + blockIdx.x * ROWS_PER_BLK + rr] = tile[bb][rr];
}

// ---------------- launch ----------------
extern "C" void kernel_launch(void* const* d_in, const int* in_sizes, int n_in,
                              void* d_out, int out_size) {
    const float* x       = (const float*)d_in[0];
    const float* ih_vals = (const float*)d_in[1];
    const float* hh_vals = (const float*)d_in[2];
    const float* hh_bias = (const float*)d_in[3];
    const int*   ih_rows = (const int*)  d_in[4];
    const int*   ih_cols = (const int*)  d_in[5];
    const int*   hh_rows = (const int*)  d_in[6];
    const int*   hh_cols = (const int*)  d_in[7];
    float* out = (float*)d_out;

    // CSR build + x transpose (all graph-capturable, deterministic work)
    k_zero_all<<<(H_DIM * BATCH + 255) / 256, 256>>>();
    k_hist<<<(NNZ_HH + 255) / 256, 256>>>(ih_rows, hh_rows);
    k_scan<<<2, 1024>>>();
    k_zero_cnt<<<(2 * H_DIM + 255) / 256, 256>>>();
    k_scatter<<<(NNZ_HH + 255) / 256, 256>>>(ih_rows, ih_cols, ih_vals,
                                             hh_rows, hh_cols, hh_vals);
    k_transpose_x<<<dim3(I_DIM / 32, BATCH / 32, T_STEPS), dim3(32, 32)>>>(x);

    // sequential RNN steps
    for (int t = 0; t < T_STEPS; t++) {
        k_step<<<H_DIM / ROWS_PER_BLK, dim3(BATCH, ROWS_PER_BLK)>>>(
            hh_bias, out, t, t & 1);
    }
}